// round 17
// baseline (speedup 1.0000x reference)
#include <cuda_runtime.h>
#include <cuda_fp16.h>
#include <cstdint>
#include <cstring>

#define B_ 8
#define H_ 64
#define W_ 64
#define C_ 256
#define NPIXTOT (B_*H_*W_)
#define NELEM (NPIXTOT*C_)

// Scratch (device globals; no allocation allowed) — all 16B-aligned for uint4 access
__device__ __align__(16) __half g_xh[NELEM];     // fp16 input
__device__ __align__(16) __half g_k1h[NELEM];    // fp16 intermediate (k branch)
__device__ __align__(16) __half g_qcath[NELEM];  // fp16 concat (q branch)
__device__ __align__(16) __half g_kh[NELEM];     // conv outputs, (b,pix,c) fp16
__device__ __align__(16) __half g_qh[NELEM];
__device__ __align__(16) __half g_vh[NELEM];
__device__ __align__(16) __half g_kT[NELEM];     // channel-first (b,c,i,j) fp16
__device__ __align__(16) __half g_qT[NELEM];
__device__ __align__(16) __half g_vT[NELEM];
__device__ __align__(16) float  g_E[NELEM];      // energy (b,c,i,k) fp32
__device__ __align__(16) __half g_P[NELEM];      // softmaxed attention (b,c,i,k) fp16
__device__ __align__(16) float  g_O[NELEM];      // attn output (b,c,i,k) fp32
// transposed fp16 weights [cout][ktot]
__device__ __align__(16) __half g_wt[1179648];

#define WT_WK   0
#define WT_WQ4  589824
#define WT_WV   655360
#define WT_WQ1  720896
#define WT_WQ2  868352
#define WT_WQ3  1015808
#define WT_WQ   1163264

__device__ __forceinline__ uint32_t h2u(__half2 h) {
    uint32_t u; memcpy(&u, &h, 4); return u;
}

__device__ __forceinline__ void mma_f16(float* d, const uint32_t* a,
                                        uint32_t b0, uint32_t b1) {
    asm volatile(
        "mma.sync.aligned.m16n8k16.row.col.f32.f16.f16.f32 "
        "{%0,%1,%2,%3}, {%4,%5,%6,%7}, {%8,%9}, {%0,%1,%2,%3};"
        : "+f"(d[0]), "+f"(d[1]), "+f"(d[2]), "+f"(d[3])
        : "r"(a[0]), "r"(a[1]), "r"(a[2]), "r"(a[3]), "r"(b0), "r"(b1));
}
__device__ __forceinline__ void ldsm4(uint32_t* r, uint32_t addr) {
    asm volatile("ldmatrix.sync.aligned.m8n8.x4.shared.b16 {%0,%1,%2,%3}, [%4];"
        : "=r"(r[0]), "=r"(r[1]), "=r"(r[2]), "=r"(r[3]) : "r"(addr));
}
__device__ __forceinline__ void ldsm4t(uint32_t* r, uint32_t addr) {
    asm volatile("ldmatrix.sync.aligned.m8n8.x4.trans.shared.b16 {%0,%1,%2,%3}, [%4];"
        : "=r"(r[0]), "=r"(r[1]), "=r"(r[2]), "=r"(r[3]) : "r"(addr));
}
__device__ __forceinline__ uint32_t scvta(const void* p) {
    return (uint32_t)__cvta_generic_to_shared(p);
}
// cp.async.cg: L1-bypass (L2 -> smem). 16B only; src-size<16 zero-fills.
__device__ __forceinline__ void cp16(uint32_t saddr, const void* gaddr, uint32_t sz) {
    asm volatile("cp.async.cg.shared.global [%0], [%1], 16, %2;"
                 :: "r"(saddr), "l"(gaddr), "r"(sz) : "memory");
}
__device__ __forceinline__ void cp_commit() {
    asm volatile("cp.async.commit_group;" ::: "memory");
}
__device__ __forceinline__ void cp_wait1() {
    asm volatile("cp.async.wait_group 1;" ::: "memory");
}

// ---------------------------------------------------------------------------
// x -> fp16 pre-pass
// ---------------------------------------------------------------------------
__global__ __launch_bounds__(256)
void x2h_kernel(const float* __restrict__ x, __half* __restrict__ xh)
{
    const int i4 = blockIdx.x * 256 + threadIdx.x;
    const float4 v = *(const float4*)&x[i4 * 4];
    __half2* o = (__half2*)&xh[i4 * 4];
    o[0] = __floats2half2_rn(v.x, v.y);
    o[1] = __floats2half2_rn(v.z, v.w);
}

// ---------------------------------------------------------------------------
// ALL weight transposes fused: one segmented kernel.
// ---------------------------------------------------------------------------
__global__ __launch_bounds__(256)
void wtrans_all(const float* __restrict__ wk,  const float* __restrict__ wq4,
                const float* __restrict__ wv,  const float* __restrict__ wq1,
                const float* __restrict__ wq2, const float* __restrict__ wq3,
                const float* __restrict__ wq,  __half* __restrict__ wt)
{
    const int idx = blockIdx.x * 256 + threadIdx.x;   // < 1179648
    const float* src; int base, COUT, KTOT;
    if      (idx < 655360)  { if (idx < 589824) { src=wk;  base=0;       COUT=256; KTOT=2304; }
                              else              { src=wq4; base=589824;  COUT=256; KTOT=256;  } }
    else if (idx < 868352)  { if (idx < 720896) { src=wv;  base=655360;  COUT=256; KTOT=256;  }
                              else              { src=wq1; base=720896;  COUT=64;  KTOT=2304; } }
    else if (idx < 1163264) { if (idx < 1015808){ src=wq2; base=868352;  COUT=64;  KTOT=2304; }
                              else              { src=wq3; base=1015808; COUT=64;  KTOT=2304; } }
    else                    {                     src=wq;  base=1163264; COUT=64;  KTOT=256;  }
    const int l  = idx - base;
    const int co = l / KTOT;
    const int kk = l - co * KTOT;
    wt[idx] = __float2half_rn(src[kk * COUT + co]);
}

// ---------------------------------------------------------------------------
// Implicit-GEMM conv via mma.sync fp16 (m16n8k16), cp.async 3-stage pipeline.
// Fragment loads via ldmatrix (A non-trans, B non-trans n16 tiles).
// ---------------------------------------------------------------------------
template<int COUT, int KS, bool OUTH>
__device__ __forceinline__
void conv_body(const __half* __restrict__ x, const __half* __restrict__ wt,
               const float* __restrict__ bias, void* __restrict__ outp,
               int coff, int ctot, int dil, int tile, int n0)
{
    constexpr int KTOT   = KS * KS * 256;
    constexpr int NCH    = KS * KS * 8;
    constexpr int BN     = (COUT == 256) ? 128 : 64;
    constexpr int WN     = BN / 2;
    constexpr int NA     = WN / 8;
    constexpr int AST    = 20;                    // uint32 words per row
    constexpr int ASTH   = 40;                    // halves per row
    constexpr int AL     = 2;
    constexpr int BL     = BN / 64;
    constexpr int STAGES = 3;

    extern __shared__ uint32_t sm32[];
    uint32_t* Asm = sm32;
    uint32_t* Bsm = sm32 + STAGES * 128 * AST;

    const int tid  = threadIdx.x;
    const int wid  = tid >> 5;
    const int lane = tid & 31;
    const int wm   = wid >> 1;
    const int wn   = wid & 1;
    const int gr   = lane >> 2;
    const int gc   = lane & 3;

    const int b  = tile >> 5;
    const int h0 = (tile & 31) * 2;

    float acc[2][NA][4];
    #pragma unroll
    for (int am = 0; am < 2; am++)
        #pragma unroll
        for (int an = 0; an < NA; an++)
            #pragma unroll
            for (int i = 0; i < 4; i++) acc[am][an][i] = 0.f;

    auto issue = [&](int ch) {
        const int st  = ch % STAGES;
        const int tap = ch >> 3;
        const int c0  = (ch & 7) * 32;
        const int dy  = (tap / KS - KS / 2) * dil;
        const int dx  = (tap % KS - KS / 2) * dil;
        uint32_t* As = Asm + st * 128 * AST;
        uint32_t* Bs = Bsm + st * BN * AST;
        #pragma unroll
        for (int i = 0; i < AL; i++) {
            const int idx = tid + i * 256;
            const int row = idx >> 2;
            const int c16 = idx & 3;
            const int ph  = row >> 6;
            const int pw  = row & 63;
            const int h_in = h0 + ph + dy;
            const int w_in = pw + dx;
            const bool valid = ((unsigned)h_in < 64u) && ((unsigned)w_in < 64u);
            const __half* src = valid
                ? &x[(((b*64 + h_in)*64 + w_in) * 256) + c0 + c16*8] : x;
            cp16(scvta(&As[row * AST + c16 * 4]), src, valid ? 16u : 0u);
        }
        const int koff = tap * 256 + c0;
        #pragma unroll
        for (int i = 0; i < BL; i++) {
            const int idx = tid + i * 256;
            const int row = idx >> 2;
            const int c16 = idx & 3;
            cp16(scvta(&Bs[row * AST + c16 * 4]),
                 &wt[(n0 + row) * KTOT + koff + c16 * 8], 16u);
        }
        cp_commit();
    };

    // ldmatrix lane->address mappings (verified in attn_gemm1/attn_gemm2)
    const int arow = (lane & 7) + ((lane & 8) ? 8 : 0);
    const int acol = (lane & 16) ? 8 : 0;
    const int brow = (lane & 7) + ((lane & 16) ? 8 : 0);
    const int bcol = (lane & 8) ? 8 : 0;

    auto compute = [&](int st) {
        const __half* Ash = (const __half*)(Asm + st * 128 * AST);
        const __half* Bsh = (const __half*)(Bsm + st * BN * AST);
        #pragma unroll
        for (int s = 0; s < 2; s++) {
            uint32_t a[2][4];
            #pragma unroll
            for (int am = 0; am < 2; am++)
                ldsm4(a[am], scvta(&Ash[(wm*32 + am*16 + arow) * ASTH + s*16 + acol]));
            #pragma unroll
            for (int ng = 0; ng < NA/2; ng++) {
                uint32_t bf[4];
                ldsm4(bf, scvta(&Bsh[(wn*WN + ng*16 + brow) * ASTH + s*16 + bcol]));
                #pragma unroll
                for (int am = 0; am < 2; am++) {
                    mma_f16(acc[am][ng*2+0], a[am], bf[0], bf[1]);
                    mma_f16(acc[am][ng*2+1], a[am], bf[2], bf[3]);
                }
            }
        }
    };

    issue(0);
    issue(1);
    for (int ch = 0; ch < NCH; ch++) {
        cp_wait1();
        __syncthreads();   // copies for stage ch visible; all warps past compute(ch-1)
        if (ch + 2 < NCH) issue(ch + 2);   // overwrites buffer of compute(ch-1)
        else              cp_commit();
        compute(ch % STAGES);
    }

    #pragma unroll
    for (int am = 0; am < 2; am++) {
        #pragma unroll
        for (int an = 0; an < NA; an++) {
            const int cl = n0 + wn*WN + an*8 + gc*2;
            const float b0v = bias[cl];
            const float b1v = bias[cl + 1];
            #pragma unroll
            for (int half = 0; half < 2; half++) {
                const int mr = wm*32 + am*16 + gr + half*8;
                const int ph = mr >> 6;
                const int pw = mr & 63;
                const int base = (((b*64 + h0 + ph)*64 + pw) * ctot) + coff + cl;
                const float o0 = acc[am][an][half*2 + 0] + b0v;
                const float o1 = acc[am][an][half*2 + 1] + b1v;
                if (OUTH) {
                    *(__half2*)&((__half*)outp)[base] = __floats2half2_rn(o0, o1);
                } else {
                    *(float2*)&((float*)outp)[base] = make_float2(o0, o1);
                }
            }
        }
    }
}

template<int COUT, int KS, bool OUTH>
__global__ __launch_bounds__(256, 3)
void conv_g(const __half* __restrict__ x, const __half* __restrict__ wt,
            const float* __restrict__ bias, void* __restrict__ out,
            int coff, int ctot, int dil)
{
    constexpr int BN = (COUT == 256) ? 128 : 64;
    conv_body<COUT, KS, OUTH>(x, wt, bias, out, coff, ctot, dil,
                              blockIdx.x, blockIdx.y * BN);
}

__global__ __launch_bounds__(256, 3)
void qconv3_g(const __half* __restrict__ x, const __half* __restrict__ wt,
              const float* __restrict__ b1, const float* __restrict__ b2,
              const float* __restrict__ b3, __half* __restrict__ out)
{
    const int z = blockIdx.z;
    const int dil = (z == 0) ? 1 : ((z == 1) ? 3 : 6);
    const float* bias = (z == 0) ? b1 : ((z == 1) ? b2 : b3);
    conv_body<64, 3, true>(x, wt + z * 64 * 2304, bias, out,
                           64 + z * 64, 256, dil, blockIdx.x, 0);
}

// ---------------------------------------------------------------------------
// fp16 transpose, 3 tensors in one launch (z = tensor*8 + b)
// ---------------------------------------------------------------------------
__global__ __launch_bounds__(256)
void transp3_h(const __half* __restrict__ kh, const __half* __restrict__ qh,
               const __half* __restrict__ vh, __half* __restrict__ kT,
               __half* __restrict__ qT, __half* __restrict__ vT)
{
    __shared__ __align__(16) __half t[64 * 72];
    const int z  = blockIdx.z;
    const int tn = z >> 3;
    const int b  = z & 7;
    const __half* in   = (tn == 0) ? kh : ((tn == 1) ? qh : vh);
    __half*       outp = (tn == 0) ? kT : ((tn == 1) ? qT : vT);
    const int p0 = blockIdx.x * 64;
    const int c0 = blockIdx.y * 64;
    const int tid = threadIdx.x;

    #pragma unroll
    for (int i = 0; i < 2; i++) {
        const int idx = tid + i * 256;
        const int r  = idx >> 3;
        const int c8 = idx & 7;
        *(uint4*)&t[r * 72 + c8 * 8] =
            *(const uint4*)&in[((b * 4096) + p0 + r) * 256 + c0 + c8 * 8];
    }
    __syncthreads();

    const int c  = tid & 63;
    const int pg = tid >> 6;
    uint4 o0, o1;
    o0.x = h2u(__halves2half2(t[(pg*16+ 0)*72 + c], t[(pg*16+ 1)*72 + c]));
    o0.y = h2u(__halves2half2(t[(pg*16+ 2)*72 + c], t[(pg*16+ 3)*72 + c]));
    o0.z = h2u(__halves2half2(t[(pg*16+ 4)*72 + c], t[(pg*16+ 5)*72 + c]));
    o0.w = h2u(__halves2half2(t[(pg*16+ 6)*72 + c], t[(pg*16+ 7)*72 + c]));
    o1.x = h2u(__halves2half2(t[(pg*16+ 8)*72 + c], t[(pg*16+ 9)*72 + c]));
    o1.y = h2u(__halves2half2(t[(pg*16+10)*72 + c], t[(pg*16+11)*72 + c]));
    o1.z = h2u(__halves2half2(t[(pg*16+12)*72 + c], t[(pg*16+13)*72 + c]));
    o1.w = h2u(__halves2half2(t[(pg*16+14)*72 + c], t[(pg*16+15)*72 + c]));
    __half* o = &outp[((b * 256) + c0 + c) * 4096 + p0 + pg * 16];
    *(uint4*)&o[0] = o0;
    *(uint4*)&o[8] = o1;
}

// ---------------------------------------------------------------------------
// gemm1: E_c[i,k2] = sum_j kT_c[i,j] * qT_c[j,k2]   (per b,c: 64x64x64)
// ---------------------------------------------------------------------------
__global__ __launch_bounds__(128)
void attn_gemm1(const __half* __restrict__ kT, const __half* __restrict__ qT,
                float* __restrict__ E)
{
    __shared__ __align__(16) __half Ks[64 * 72];
    __shared__ __align__(16) __half Qs[64 * 72];
    const int bc   = blockIdx.x;
    const int tid  = threadIdx.x;
    const int wid  = tid >> 5;
    const int lane = tid & 31;

    const __half* kg = kT + bc * 4096;
    const __half* qg = qT + bc * 4096;
    #pragma unroll
    for (int i = 0; i < 4; i++) {
        const int idx = tid + i * 128;
        const int r  = idx >> 3;
        const int c8 = idx & 7;
        *(uint4*)&Ks[r * 72 + c8 * 8] = *(const uint4*)&kg[r * 64 + c8 * 8];
        *(uint4*)&Qs[r * 72 + c8 * 8] = *(const uint4*)&qg[r * 64 + c8 * 8];
    }
    __syncthreads();

    float acc[8][4];
    #pragma unroll
    for (int i = 0; i < 8; i++)
        #pragma unroll
        for (int j = 0; j < 4; j++) acc[i][j] = 0.f;

    const int i0   = wid * 16;
    const int arow = (lane & 7) + ((lane & 8) ? 8 : 0);
    const int acol = (lane & 16) ? 8 : 0;
    const int brow = (lane & 7) + ((lane & 8) ? 8 : 0);
    const int bcol = (lane & 16) ? 8 : 0;

    #pragma unroll
    for (int kp = 0; kp < 4; kp++) {
        uint32_t a[4];
        ldsm4(a, scvta(&Ks[(i0 + arow) * 72 + kp * 16 + acol]));
        #pragma unroll
        for (int np = 0; np < 4; np++) {
            uint32_t bf[4];
            ldsm4t(bf, scvta(&Qs[(kp * 16 + brow) * 72 + np * 16 + bcol]));
            mma_f16(acc[np * 2 + 0], a, bf[0], bf[1]);
            mma_f16(acc[np * 2 + 1], a, bf[2], bf[3]);
        }
    }

    float* eb = E + bc * 4096;
    const int r0 = i0 + (lane >> 2);
    const int cb = (lane & 3) * 2;
    #pragma unroll
    for (int na = 0; na < 8; na++) {
        const int col = na * 8 + cb;
        *(float2*)&eb[r0 * 64 + col]       = make_float2(acc[na][0], acc[na][1]);
        *(float2*)&eb[(r0 + 8) * 64 + col] = make_float2(acc[na][2], acc[na][3]);
    }
}

// ---------------------------------------------------------------------------
// Softmax over channel axis, block-cooperative (8 c-groups x 32 ik / block)
// ---------------------------------------------------------------------------
__global__ __launch_bounds__(256)
void softmax_c_kernel(const float* __restrict__ E, __half* __restrict__ P)
{
    __shared__ float red[8][32];
    const int b   = blockIdx.x >> 7;
    const int ik0 = (blockIdx.x & 127) * 32;
    const int ikl = threadIdx.x & 31;
    const int cg  = threadIdx.x >> 5;
    const int ik  = ik0 + ikl;

    const float* e = E + ((size_t)(b * 256 + cg * 32)) * 4096 + ik;
    float v[32];
    float m = -1e30f;
    #pragma unroll
    for (int j = 0; j < 32; j++) { v[j] = e[j * 4096]; m = fmaxf(m, v[j]); }
    red[cg][ikl] = m;
    __syncthreads();
    float M = red[0][ikl];
    #pragma unroll
    for (int g = 1; g < 8; g++) M = fmaxf(M, red[g][ikl]);
    __syncthreads();

    float s = 0.f;
    #pragma unroll
    for (int j = 0; j < 32; j++) { v[j] = __expf(v[j] - M); s += v[j]; }
    red[cg][ikl] = s;
    __syncthreads();
    float S = red[0][ikl];
    #pragma unroll
    for (int g = 1; g < 8; g++) S += red[g][ikl];
    const float inv = 1.0f / S;

    __half* p = P + ((size_t)(b * 256 + cg * 32)) * 4096 + ik;
    #pragma unroll
    for (int j = 0; j < 32; j++) p[j * 4096] = __float2half(v[j] * inv);
}

// ---------------------------------------------------------------------------
// gemm2: O_c[i2,k2] = sum_j P_c[j,i2] * vT_c[k2,j]
// ---------------------------------------------------------------------------
__global__ __launch_bounds__(128)
void attn_gemm2(const __half* __restrict__ P, const __half* __restrict__ vT,
                float* __restrict__ O)
{
    __shared__ __align__(16) __half Ps[64 * 72];
    __shared__ __align__(16) __half Vs[64 * 72];
    const int bc   = blockIdx.x;
    const int tid  = threadIdx.x;
    const int wid  = tid >> 5;
    const int lane = tid & 31;

    const __half* pg = P  + bc * 4096;
    const __half* vg = vT + bc * 4096;
    #pragma unroll
    for (int i = 0; i < 4; i++) {
        const int idx = tid + i * 128;
        const int r  = idx >> 3;
        const int c8 = idx & 7;
        *(uint4*)&Ps[r * 72 + c8 * 8] = *(const uint4*)&pg[r * 64 + c8 * 8];
        *(uint4*)&Vs[r * 72 + c8 * 8] = *(const uint4*)&vg[r * 64 + c8 * 8];
    }
    __syncthreads();

    float acc[8][4];
    #pragma unroll
    for (int i = 0; i < 8; i++)
        #pragma unroll
        for (int j = 0; j < 4; j++) acc[i][j] = 0.f;

    const int i0   = wid * 16;
    const int arow = (lane & 7) + ((lane & 16) ? 8 : 0);
    const int acol = i0 + ((lane & 8) ? 8 : 0);
    const int brow = (lane & 7) + ((lane & 16) ? 8 : 0);
    const int bcol = (lane & 8) ? 8 : 0;

    #pragma unroll
    for (int kp = 0; kp < 4; kp++) {
        uint32_t a[4];
        ldsm4t(a, scvta(&Ps[(kp * 16 + arow) * 72 + acol]));
        #pragma unroll
        for (int np = 0; np < 4; np++) {
            uint32_t bf[4];
            ldsm4(bf, scvta(&Vs[(np * 16 + brow) * 72 + kp * 16 + bcol]));
            mma_f16(acc[np * 2 + 0], a, bf[0], bf[1]);
            mma_f16(acc[np * 2 + 1], a, bf[2], bf[3]);
        }
    }

    float* ob = O + bc * 4096;
    const int r0 = i0 + (lane >> 2);
    const int cb = (lane & 3) * 2;
    #pragma unroll
    for (int na = 0; na < 8; na++) {
        const int col = na * 8 + cb;
        *(float2*)&ob[r0 * 64 + col]       = make_float2(acc[na][0], acc[na][1]);
        *(float2*)&ob[(r0 + 8) * 64 + col] = make_float2(acc[na][2], acc[na][3]);
    }
}

// ---------------------------------------------------------------------------
// Final: out[b,ik,c] = gamma * O[b,c,ik] + x[b,ik,c]  (tile-transposed)
// ---------------------------------------------------------------------------
__global__ __launch_bounds__(256)
void final_merge(const float* __restrict__ O, const float* __restrict__ x,
                 const float* __restrict__ gammap, float* __restrict__ outp)
{
    __shared__ __align__(16) float t[64 * 68];
    const int b   = blockIdx.z;
    const int ik0 = blockIdx.x * 64;
    const int c0  = blockIdx.y * 64;
    const int tid = threadIdx.x;

    #pragma unroll
    for (int i = 0; i < 4; i++) {
        const int idx = tid + i * 256;
        const int r   = idx >> 4;
        const int c16 = idx & 15;
        *(float4*)&t[r * 68 + c16 * 4] =
            *(const float4*)&O[((size_t)(b * 256 + c0 + r)) * 4096 + ik0 + c16 * 4];
    }
    __syncthreads();

    const float gm = gammap[0];
    const int ik = tid & 63;
    const int cg = tid >> 6;
    const int gbase = ((b * 4096) + ik0 + ik) * 256 + c0 + cg * 16;
    #pragma unroll
    for (int i = 0; i < 16; i += 4) {
        const int c = cg * 16 + i;
        const float4 xv = *(const float4*)&x[gbase + i];
        float4 o;
        o.x = gm * t[(c + 0) * 68 + ik] + xv.x;
        o.y = gm * t[(c + 1) * 68 + ik] + xv.y;
        o.z = gm * t[(c + 2) * 68 + ik] + xv.z;
        o.w = gm * t[(c + 3) * 68 + ik] + xv.w;
        *(float4*)&outp[gbase + i] = o;
    }
}

// ---------------------------------------------------------------------------
extern "C" void kernel_launch(void* const* d_in, const int* in_sizes, int n_in,
                              void* d_out, int out_size)
{
    const float* x    = (const float*)d_in[0];
    const float* wq   = (const float*)d_in[1];
    const float* bq   = (const float*)d_in[2];
    const float* wq1  = (const float*)d_in[3];
    const float* bq1  = (const float*)d_in[4];
    const float* wq2  = (const float*)d_in[5];
    const float* bq2  = (const float*)d_in[6];
    const float* wq3  = (const float*)d_in[7];
    const float* bq3  = (const float*)d_in[8];
    const float* wq4  = (const float*)d_in[9];
    const float* bq4  = (const float*)d_in[10];
    const float* wk   = (const float*)d_in[11];
    const float* bk   = (const float*)d_in[12];
    const float* wv   = (const float*)d_in[13];
    const float* bv   = (const float*)d_in[14];
    const float* gamma= (const float*)d_in[15];
    float* out = (float*)d_out;

    __half *xh, *k1h, *qcath, *kh, *qh, *vh, *kT, *qT, *vT, *P, *wt;
    float *E, *O;
    cudaGetSymbolAddress((void**)&xh,    g_xh);
    cudaGetSymbolAddress((void**)&k1h,   g_k1h);
    cudaGetSymbolAddress((void**)&qcath, g_qcath);
    cudaGetSymbolAddress((void**)&kh,    g_kh);
    cudaGetSymbolAddress((void**)&qh,    g_qh);
    cudaGetSymbolAddress((void**)&vh,    g_vh);
    cudaGetSymbolAddress((void**)&kT,    g_kT);
    cudaGetSymbolAddress((void**)&qT,    g_qT);
    cudaGetSymbolAddress((void**)&vT,    g_vT);
    cudaGetSymbolAddress((void**)&E,     g_E);
    cudaGetSymbolAddress((void**)&P,     g_P);
    cudaGetSymbolAddress((void**)&O,     g_O);
    cudaGetSymbolAddress((void**)&wt,    g_wt);

    const int SM256 = 3 * (128 + 128) * 20 * 4;   // 61440
    const int SM64  = 3 * (128 + 64)  * 20 * 4;   // 46080
    cudaFuncSetAttribute(conv_g<256,3,true>, cudaFuncAttributeMaxDynamicSharedMemorySize, SM256);
    cudaFuncSetAttribute(conv_g<256,1,true>, cudaFuncAttributeMaxDynamicSharedMemorySize, SM256);
    cudaFuncSetAttribute(conv_g<64,1,true>,  cudaFuncAttributeMaxDynamicSharedMemorySize, SM64);
    cudaFuncSetAttribute(qconv3_g,           cudaFuncAttributeMaxDynamicSharedMemorySize, SM64);

    const dim3 cblk(256);

    // pre-passes (fused: 2 launches)
    x2h_kernel<<<NELEM / 4 / 256, 256>>>(x, xh);
    wtrans_all<<<1179648 / 256, 256>>>(wk, wq4, wv, wq1, wq2, wq3, wq, wt);

    // convs (all fp16 out)
    conv_g<256,3,true><<<dim3(256,2), cblk, SM256>>>(xh,  wt + WT_WK, bk, k1h, 0, 256, 1);
    conv_g<256,3,true><<<dim3(256,2), cblk, SM256>>>(k1h, wt + WT_WK, bk, kh,  0, 256, 1);
    conv_g<64,1,true><<<dim3(256,1), cblk, SM64>>>(xh, wt + WT_WQ, bq, qcath, 0, 256, 1);
    qconv3_g<<<dim3(256,1,3), cblk, SM64>>>(xh, wt + WT_WQ1, bq1, bq2, bq3, qcath);
    conv_g<256,1,true><<<dim3(256,2), cblk, SM256>>>(qcath, wt + WT_WQ4, bq4, qh, 0, 256, 1);
    conv_g<256,1,true><<<dim3(256,2), cblk, SM256>>>(xh,    wt + WT_WV,  bv,  vh, 0, 256, 1);

    // attention (MMA path)
    transp3_h<<<dim3(64,4,24), 256>>>(kh, qh, vh, kT, qT, vT);
    attn_gemm1<<<2048, 128>>>(kT, qT, E);
    softmax_c_kernel<<<1024, 256>>>(E, P);
    attn_gemm2<<<2048, 128>>>(P, vT, O);
    final_merge<<<dim3(64,4,8), 256>>>(O, x, gamma, out);
}